// round 1
// baseline (speedup 1.0000x reference)
#include <cuda_runtime.h>

#define BATCH   4096
#define IN_W    1024
#define DEPTH   8
#define BLOCKS  64
#define COLB    16
#define NACT    8
#define GROW    512
#define TOTAL   5120
#define OUT_W   512

// 84 MB scratch state (allowed: static __device__ global, no runtime alloc)
__device__ float g_data[(size_t)TOTAL * BATCH];

typedef unsigned long long ull;

__device__ __forceinline__ ull pk2(float x, float y) {
    ull r; asm("mov.b64 %0, {%1, %2};" : "=l"(r) : "f"(x), "f"(y)); return r;
}
__device__ __forceinline__ void upk2(ull v, float& x, float& y) {
    asm("mov.b64 {%0, %1}, %2;" : "=f"(x), "=f"(y) : "l"(v));
}
// Packed f32x2 FMA/MUL — Blackwell FFMA2 path (only reachable via PTX)
__device__ __forceinline__ ull fma2(ull a, ull b, ull c) {
    ull d; asm("fma.rn.f32x2 %0, %1, %2, %3;" : "=l"(d) : "l"(a), "l"(b), "l"(c)); return d;
}
__device__ __forceinline__ ull mul2(ull a, ull b) {
    ull d; asm("mul.rn.f32x2 %0, %1, %2;" : "=l"(d) : "l"(a), "l"(b)); return d;
}

__device__ __forceinline__ float actf(float p) {
    return 0.5f * (p + sqrtf(fmaf(p, p, 1.0f)));
}

// ---------------------------------------------------------------------------
// Init: g_data[0:1024] = scales[:,None] * input
// ---------------------------------------------------------------------------
__global__ void init_kernel(const float* __restrict__ inp,
                            const float* __restrict__ scales) {
    int i = blockIdx.x * blockDim.x + threadIdx.x;     // float4 index
    const int n4 = IN_W * BATCH / 4;
    if (i >= n4) return;
    int row = i / (BATCH / 4);
    float4 v = ((const float4*)inp)[i];
    float s = scales[row];
    v.x *= s; v.y *= s; v.z *= s; v.w *= s;
    ((float4*)g_data)[i] = v;
}

// ---------------------------------------------------------------------------
// One butterfly module. Each CUDA block: (butterfly block blk) x (512 batch
// cols). Each thread owns 4 batch columns of all 16 rows, packed as f32x2
// pairs, entire transform in registers.
// ---------------------------------------------------------------------------
template<bool LAST>
__global__ __launch_bounds__(128)
void module_kernel(const float* __restrict__ angles,  // [8][512] this module
                   const float* __restrict__ biases,  // [512]    this module
                   const int*   __restrict__ idx,     // [1024]   this module
                   int mod,
                   float* __restrict__ out_ext)       // d_out for LAST
{
    const int blk = blockIdx.y;
    const int tid = threadIdx.x;

    __shared__ int   s_idx[16];
    __shared__ float s_bias[NACT];
    __shared__ ull   s_c[64], s_s[64], s_ns[64];   // [layer*8 + angle]

    if (tid < 16) s_idx[tid]  = idx[blk * 16 + tid];
    if (tid < 8)  s_bias[tid] = biases[blk * 8 + tid];
    if (tid < 64) {
        int L = tid >> 3, a = tid & 7;
        float ang = angles[L * 512 + blk * 8 + a];
        float sn, cs;
        sincosf(ang, &sn, &cs);
        s_c[tid]  = pk2(cs, cs);
        s_s[tid]  = pk2(sn, sn);
        s_ns[tid] = pk2(-sn, -sn);
    }
    __syncthreads();

    const int b = (blockIdx.x * 128 + tid) * 4;   // first of 4 batch cols

    // Gather 16 rows (LDG.128 each, 16 independent loads -> high MLP)
    ull v[32];
    #pragma unroll
    for (int j = 0; j < 16; j++) {
        ulonglong2 u = *(const ulonglong2*)(g_data + (size_t)s_idx[j] * BATCH + b);
        v[2 * j] = u.x; v[2 * j + 1] = u.y;
    }

    // 4 IN rotation layers, strides 1,2,4,8 (bits 0..3), all in registers
    #pragma unroll
    for (int k = 0; k < 4; k++) {
        const int st = 1 << k;
        #pragma unroll
        for (int g = 0; g < 16; g += 2 * st) {
            #pragma unroll
            for (int j = 0; j < st; j++) {
                const int lo = g + j, hi = lo + st;
                const int ai = k * 8 + (g >> 1) + j;
                const ull c2 = s_c[ai], s2 = s_s[ai], n2 = s_ns[ai];
                #pragma unroll
                for (int h = 0; h < 2; h++) {
                    ull xl = v[2 * lo + h], xh = v[2 * hi + h];
                    v[2 * lo + h] = fma2(c2, xl, mul2(s2, xh));
                    v[2 * hi + h] = fma2(n2, xl, mul2(c2, xh));
                }
            }
        }
    }

    // Activation on rows 0..7; write act rows out (d_out for last module)
    float* actbase = LAST ? out_ext
                          : (g_data + (size_t)(IN_W + GROW * mod) * BATCH);
    #pragma unroll
    for (int u = 0; u < NACT; u++) {
        const float bb = s_bias[u];
        float x0, x1, x2, x3;
        upk2(v[2 * u], x0, x1);
        upk2(v[2 * u + 1], x2, x3);
        x0 = actf(x0 + bb); x1 = actf(x1 + bb);
        x2 = actf(x2 + bb); x3 = actf(x3 + bb);
        v[2 * u]     = pk2(x0, x1);
        v[2 * u + 1] = pk2(x2, x3);
        float4 o = make_float4(x0, x1, x2, x3);
        *(float4*)(actbase + (size_t)(blk * NACT + u) * BATCH + b) = o;
    }

    if (!LAST) {
        // 4 OUT rotation layers (angle layers 4..7, same strides 1,2,4,8)
        #pragma unroll
        for (int k = 0; k < 4; k++) {
            const int st = 1 << k;
            #pragma unroll
            for (int g = 0; g < 16; g += 2 * st) {
                #pragma unroll
                for (int j = 0; j < st; j++) {
                    const int lo = g + j, hi = lo + st;
                    const int ai = (4 + k) * 8 + (g >> 1) + j;
                    const ull c2 = s_c[ai], s2 = s_s[ai], n2 = s_ns[ai];
                    #pragma unroll
                    for (int h = 0; h < 2; h++) {
                        ull xl = v[2 * lo + h], xh = v[2 * hi + h];
                        v[2 * lo + h] = fma2(c2, xl, mul2(s2, xh));
                        v[2 * hi + h] = fma2(n2, xl, mul2(c2, xh));
                    }
                }
            }
        }
        // Scatter back
        #pragma unroll
        for (int j = 0; j < 16; j++) {
            ulonglong2 u;
            u.x = v[2 * j]; u.y = v[2 * j + 1];
            *(ulonglong2*)(g_data + (size_t)s_idx[j] * BATCH + b) = u;
        }
    }
}

// ---------------------------------------------------------------------------
extern "C" void kernel_launch(void* const* d_in, const int* in_sizes, int n_in,
                              void* d_out, int out_size) {
    const float* input   = (const float*)d_in[0];   // (1024, 4096)
    const float* scales  = (const float*)d_in[1];   // (1024,)
    const float* angles  = (const float*)d_in[2];   // (8, 8, 512)
    const float* biases  = (const float*)d_in[3];   // (8, 512)
    const int*   indices = (const int*)d_in[4];     // (8, 1024)
    float* out = (float*)d_out;                     // (512, 4096)

    {
        const int n4 = IN_W * BATCH / 4;
        init_kernel<<<(n4 + 255) / 256, 256>>>(input, scales);
    }

    dim3 grid(BATCH / (128 * 4), BLOCKS);   // (8, 64)
    for (int m = 0; m < DEPTH; m++) {
        const float* ang = angles + (size_t)m * 8 * 512;
        const float* bia = biases + (size_t)m * 512;
        const int*   ix  = indices + (size_t)m * 1024;
        if (m < DEPTH - 1)
            module_kernel<false><<<grid, 128>>>(ang, bia, ix, m, nullptr);
        else
            module_kernel<true><<<grid, 128>>>(ang, bia, ix, m, out);
    }
}

// round 2
// speedup vs baseline: 1.1975x; 1.1975x over previous
#include <cuda_runtime.h>

#define BATCH   4096
#define IN_W    1024
#define DEPTH   8
#define BLOCKS  64
#define COLB    16
#define NACT    8
#define GROW    512
#define TOTAL   5120
#define OUT_W   512

// 84 MB scratch state (static __device__ global: allowed, no runtime alloc)
__device__ float g_data[(size_t)TOTAL * BATCH];

typedef unsigned long long ull;

__device__ __forceinline__ ull pk2(float x, float y) {
    ull r; asm("mov.b64 %0, {%1, %2};" : "=l"(r) : "f"(x), "f"(y)); return r;
}
__device__ __forceinline__ void upk2(ull v, float& x, float& y) {
    asm("mov.b64 {%0, %1}, %2;" : "=f"(x), "=f"(y) : "l"(v));
}
// Packed f32x2 FMA/MUL — Blackwell FFMA2 path (only reachable via PTX)
__device__ __forceinline__ ull fma2(ull a, ull b, ull c) {
    ull d; asm("fma.rn.f32x2 %0, %1, %2, %3;" : "=l"(d) : "l"(a), "l"(b), "l"(c)); return d;
}
__device__ __forceinline__ ull mul2(ull a, ull b) {
    ull d; asm("mul.rn.f32x2 %0, %1, %2;" : "=l"(d) : "l"(a), "l"(b)); return d;
}

__device__ __forceinline__ float actf(float p) {
    return 0.5f * (p + sqrtf(fmaf(p, p, 1.0f)));
}

// ---------------------------------------------------------------------------
// Init: g_data[0:1024] = scales[:,None] * input
// ---------------------------------------------------------------------------
__global__ void init_kernel(const float* __restrict__ inp,
                            const float* __restrict__ scales) {
    int i = blockIdx.x * blockDim.x + threadIdx.x;     // float4 index
    const int n4 = IN_W * BATCH / 4;
    if (i >= n4) return;
    int row = i / (BATCH / 4);
    float4 v = ((const float4*)inp)[i];
    float s = scales[row];
    v.x *= s; v.y *= s; v.z *= s; v.w *= s;
    ((float4*)g_data)[i] = v;
}

// ---------------------------------------------------------------------------
// One butterfly module. Each CUDA block: (butterfly block blk) x (256 batch
// cols). Each thread owns 2 batch columns of all 16 rows, one f32x2 per row,
// entire transform in registers. 2 cols/thread keeps regs low -> high occ.
// ---------------------------------------------------------------------------
template<bool LAST>
__global__ __launch_bounds__(128, 6)
void module_kernel(const float* __restrict__ angles,  // [8][512] this module
                   const float* __restrict__ biases,  // [512]    this module
                   const int*   __restrict__ idx,     // [1024]   this module
                   int mod,
                   float* __restrict__ out_ext)       // d_out for LAST
{
    const int blk = blockIdx.y;
    const int tid = threadIdx.x;

    __shared__ int   s_idx[16];
    __shared__ float s_bias[NACT];
    __shared__ ull   s_c[64], s_s[64], s_ns[64];   // [layer*8 + angle]

    if (tid < 16) s_idx[tid]  = idx[blk * 16 + tid];
    if (tid < 8)  s_bias[tid] = biases[blk * 8 + tid];
    if (tid < 64) {
        int L = tid >> 3, a = tid & 7;
        float ang = angles[L * 512 + blk * 8 + a];
        float sn, cs;
        sincosf(ang, &sn, &cs);
        s_c[tid]  = pk2(cs, cs);
        s_s[tid]  = pk2(sn, sn);
        s_ns[tid] = pk2(-sn, -sn);
    }
    __syncthreads();

    const int b = (blockIdx.x * 128 + tid) * 2;   // first of 2 batch cols

    // Gather 16 rows (16 independent LDG.64 -> MLP=16)
    ull v[16];
    #pragma unroll
    for (int j = 0; j < 16; j++)
        v[j] = *(const ull*)(g_data + (size_t)s_idx[j] * BATCH + b);

    // 4 IN rotation layers, strides 1,2,4,8 (bits 0..3), all in registers
    #pragma unroll
    for (int k = 0; k < 4; k++) {
        const int st = 1 << k;
        #pragma unroll
        for (int g = 0; g < 16; g += 2 * st) {
            #pragma unroll
            for (int j = 0; j < st; j++) {
                const int lo = g + j, hi = lo + st;
                const int ai = k * 8 + (g >> 1) + j;
                const ull c2 = s_c[ai], s2 = s_s[ai], n2 = s_ns[ai];
                ull xl = v[lo], xh = v[hi];
                v[lo] = fma2(c2, xl, mul2(s2, xh));
                v[hi] = fma2(n2, xl, mul2(c2, xh));
            }
        }
    }

    // Activation on rows 0..7; write act rows out (d_out for last module)
    float* actbase = LAST ? out_ext
                          : (g_data + (size_t)(IN_W + GROW * mod) * BATCH);
    #pragma unroll
    for (int u = 0; u < NACT; u++) {
        const float bb = s_bias[u];
        float x0, x1;
        upk2(v[u], x0, x1);
        x0 = actf(x0 + bb); x1 = actf(x1 + bb);
        v[u] = pk2(x0, x1);
        *(ull*)(actbase + (size_t)(blk * NACT + u) * BATCH + b) = v[u];
    }

    if (!LAST) {
        // 4 OUT rotation layers (angle layers 4..7, same strides 1,2,4,8)
        #pragma unroll
        for (int k = 0; k < 4; k++) {
            const int st = 1 << k;
            #pragma unroll
            for (int g = 0; g < 16; g += 2 * st) {
                #pragma unroll
                for (int j = 0; j < st; j++) {
                    const int lo = g + j, hi = lo + st;
                    const int ai = (4 + k) * 8 + (g >> 1) + j;
                    const ull c2 = s_c[ai], s2 = s_s[ai], n2 = s_ns[ai];
                    ull xl = v[lo], xh = v[hi];
                    v[lo] = fma2(c2, xl, mul2(s2, xh));
                    v[hi] = fma2(n2, xl, mul2(c2, xh));
                }
            }
        }
        // Scatter back (16 independent STG.64)
        #pragma unroll
        for (int j = 0; j < 16; j++)
            *(ull*)(g_data + (size_t)s_idx[j] * BATCH + b) = v[j];
    }
}

// ---------------------------------------------------------------------------
extern "C" void kernel_launch(void* const* d_in, const int* in_sizes, int n_in,
                              void* d_out, int out_size) {
    const float* input   = (const float*)d_in[0];   // (1024, 4096)
    const float* scales  = (const float*)d_in[1];   // (1024,)
    const float* angles  = (const float*)d_in[2];   // (8, 8, 512)
    const float* biases  = (const float*)d_in[3];   // (8, 512)
    const int*   indices = (const int*)d_in[4];     // (8, 1024)
    float* out = (float*)d_out;                     // (512, 4096)

    {
        const int n4 = IN_W * BATCH / 4;
        init_kernel<<<(n4 + 255) / 256, 256>>>(input, scales);
    }

    dim3 grid(BATCH / (128 * 2), BLOCKS);   // (16, 64) = 1024 blocks
    for (int m = 0; m < DEPTH; m++) {
        const float* ang = angles + (size_t)m * 8 * 512;
        const float* bia = biases + (size_t)m * 512;
        const int*   ix  = indices + (size_t)m * 1024;
        if (m < DEPTH - 1)
            module_kernel<false><<<grid, 128>>>(ang, bia, ix, m, nullptr);
        else
            module_kernel<true><<<grid, 128>>>(ang, bia, ix, m, out);
    }
}